// round 4
// baseline (speedup 1.0000x reference)
#include <cuda_runtime.h>
#include <cstdint>

#define CCLS 8192
#define BSZ  512
#define HH   8
#define RG   8                       // rows per product group (one log per 8 rows)
#define THREADS 128
#define TILEW 512                    // floats per block-tile row (128 thr x 4)
#define NCB   (CCLS / TILEW)         // 16 column blocks
#define NRG   (BSZ / RG)             // 64 row groups
#define NBLK  (NCB * NRG)            // 1024 blocks
#define C4    (CCLS / 4)             // 2048 global float4 columns

__device__ float    g_part[NBLK];
__device__ unsigned g_cnt = 0;       // wraps each full grid -> graph-replay-safe

__device__ __forceinline__ unsigned smem_u32(const void* p) {
    unsigned a;
    asm("{ .reg .u64 t; cvta.to.shared.u64 t, %1; cvt.u32.u64 %0, t; }"
        : "=r"(a) : "l"(p));
    return a;
}
__device__ __forceinline__ unsigned long long pack2(unsigned a, unsigned b) {
    unsigned long long r;
    asm("mov.b64 %0, {%1, %2};" : "=l"(r) : "r"(a), "r"(b));
    return r;
}
__device__ __forceinline__ void unpack2(unsigned long long v, unsigned& a, unsigned& b) {
    asm("mov.b64 {%0, %1}, %2;" : "=r"(a), "=r"(b) : "l"(v));
}
__device__ __forceinline__ unsigned long long fma2(unsigned long long a,
                                                   unsigned long long b,
                                                   unsigned long long c) {
    unsigned long long d;
    asm("fma.rn.f32x2 %0, %1, %2, %3;" : "=l"(d) : "l"(a), "l"(b), "l"(c));
    return d;
}

// Single fused kernel, TMA-staged:
//   8x2KB pred rows + 8x2KB true rows -> smem via cp.async.bulk (no register
//   pressure => deep MLP), w[c]=sum_h lam[h]*La[h][c] via L2-hot LDG overlapped
//   with the bulk copies, then prod_c = PROD_r (1-|p-yt|), one log2 per column,
//   weighted block reduction, last-block finish.
__global__ void __launch_bounds__(THREADS)
k_fused(const float* __restrict__ yp, const float* __restrict__ yt,
        const float* __restrict__ La, const float* __restrict__ lam,
        float* __restrict__ out) {
    __shared__ alignas(16) float sp[RG][TILEW];
    __shared__ alignas(16) float st[RG][TILEW];
    __shared__ alignas(8) unsigned long long mbar;
    __shared__ float shred[THREADS / 32];
    __shared__ bool isLast;

    const int tid = threadIdx.x;
    const int cb  = blockIdx.x & (NCB - 1);
    const int rg  = blockIdx.x >> 4;               // log2(NCB)=4
    const unsigned mb = smem_u32(&mbar);

    if (tid == 0) {
        asm volatile("mbarrier.init.shared::cta.b64 [%0], 1;" :: "r"(mb) : "memory");
    }
    __syncthreads();

    if (tid == 0) {
        asm volatile("mbarrier.arrive.expect_tx.shared::cta.b64 _, [%0], %1;"
                     :: "r"(mb), "r"(2 * RG * TILEW * 4) : "memory");
        const size_t rowbase = (size_t)rg * RG * CCLS + (size_t)cb * TILEW;
#pragma unroll
        for (int r = 0; r < RG; r++) {
            const float* srcP = yp + rowbase + (size_t)r * CCLS;
            const float* srcT = yt + rowbase + (size_t)r * CCLS;
            asm volatile("cp.async.bulk.shared::cta.global.mbarrier::complete_tx::bytes"
                         " [%0], [%1], %2, [%3];"
                         :: "r"(smem_u32(&sp[r][0])), "l"(srcP),
                            "n"(TILEW * 4), "r"(mb) : "memory");
            asm volatile("cp.async.bulk.shared::cta.global.mbarrier::complete_tx::bytes"
                         " [%0], [%1], %2, [%3];"
                         :: "r"(smem_u32(&st[r][0])), "l"(srcT),
                            "n"(TILEW * 4), "r"(mb) : "memory");
        }
    }

    // ---- weights (overlaps with in-flight bulk copies) ----
    const int c4 = cb * (TILEW / 4) + tid;          // global float4 column
    const float4* La4 = (const float4*)La;
    float4 lamA = ((const float4*)lam)[0];
    float4 lamB = ((const float4*)lam)[1];
    float lm[HH] = {lamA.x, lamA.y, lamA.z, lamA.w, lamB.x, lamB.y, lamB.z, lamB.w};
    float4 w4 = make_float4(0.f, 0.f, 0.f, 0.f);
#pragma unroll
    for (int h = 0; h < HH; h++) {
        float4 a = La4[(size_t)h * C4 + c4];
        w4.x = fmaf(lm[h], a.x, w4.x);
        w4.y = fmaf(lm[h], a.y, w4.y);
        w4.z = fmaf(lm[h], a.z, w4.z);
        w4.w = fmaf(lm[h], a.w, w4.w);
    }

    // ---- wait for the tile (acquire) ----
    {
        unsigned done;
        asm volatile(
            "{\n\t.reg .pred p;\n\t"
            "mbarrier.try_wait.parity.acquire.cta.shared::cta.b64 p, [%1], 0;\n\t"
            "selp.b32 %0, 1, 0, p;\n\t}"
            : "=r"(done) : "r"(mb) : "memory");
        if (!done) {
            asm volatile(
                "{\n\t.reg .pred P1;\n\t"
                "W%=:\n\t"
                "mbarrier.try_wait.parity.acquire.cta.shared::cta.b64 P1, [%0], 0, 0x989680;\n\t"
                "@P1 bra.uni D%=;\n\t"
                "bra.uni W%=;\n\t"
                "D%=:\n\t}"
                :: "r"(mb) : "memory");
        }
    }

    // ---- product over 8 rows from smem, two f32x2 chains ----
    const unsigned long long NEG1 = 0xBF800000BF800000ull;
    const unsigned long long SGN  = 0x8000000080000000ull;
    unsigned long long prod01 = 0x3F8000003F800000ull;
    unsigned long long prod23 = 0x3F8000003F800000ull;
#pragma unroll
    for (int r = 0; r < RG; r++) {
        float4 pv = *(const float4*)&sp[r][tid * 4];
        float4 tv = *(const float4*)&st[r][tid * 4];
        unsigned long long p01 = pack2(__float_as_uint(pv.x), __float_as_uint(pv.y));
        unsigned long long p23 = pack2(__float_as_uint(pv.z), __float_as_uint(pv.w));
        unsigned long long t01 = pack2(__float_as_uint(tv.x), __float_as_uint(tv.y));
        unsigned long long t23 = pack2(__float_as_uint(tv.z), __float_as_uint(tv.w));
        unsigned long long d01 = fma2(t01, NEG1, p01) | SGN;   // -|p-yt|
        unsigned long long d23 = fma2(t23, NEG1, p23) | SGN;
        prod01 = fma2(d01, prod01, prod01);                    // *= (1-|d|)
        prod23 = fma2(d23, prod23, prod23);
    }

    unsigned a0, a1, a2, a3;
    unpack2(prod01, a0, a1);
    unpack2(prod23, a2, a3);
    const float CL2 = -144.26950408889634f;   // -100/ln2
    float l, acc;
    l   = fmaxf(__log2f(__uint_as_float(a0)), CL2); acc = l * w4.x;
    l   = fmaxf(__log2f(__uint_as_float(a1)), CL2); acc = fmaf(l, w4.y, acc);
    l   = fmaxf(__log2f(__uint_as_float(a2)), CL2); acc = fmaf(l, w4.z, acc);
    l   = fmaxf(__log2f(__uint_as_float(a3)), CL2); acc = fmaf(l, w4.w, acc);

    // ---- block reduction (128 threads) ----
#pragma unroll
    for (int o = 16; o; o >>= 1) acc += __shfl_xor_sync(0xFFFFFFFFu, acc, o);
    if ((tid & 31) == 0) shred[tid >> 5] = acc;
    __syncthreads();
    if (tid == 0) {
        float v = shred[0] + shred[1] + shred[2] + shred[3];
        g_part[blockIdx.x] = v;
    }

    // ---- last-block final reduction ----
    __threadfence();
    if (tid == 0) {
        unsigned t = atomicInc(&g_cnt, NBLK - 1);
        isLast = (t == NBLK - 1);
    }
    __syncthreads();
    if (isLast) {
        float v = 0.f;
#pragma unroll
        for (int i = 0; i < NBLK / THREADS; i++)
            v += g_part[tid + i * THREADS];
#pragma unroll
        for (int o = 16; o; o >>= 1) v += __shfl_xor_sync(0xFFFFFFFFu, v, o);
        if ((tid & 31) == 0) shred[tid >> 5] = v;
        __syncthreads();
        if (tid == 0) {
            float s = shred[0] + shred[1] + shred[2] + shred[3];
            out[0] = s * (-0.69314718055994531f / (float)CCLS);
        }
    }
}

extern "C" void kernel_launch(void* const* d_in, const int* in_sizes, int n_in,
                              void* d_out, int out_size) {
    const float* y_pred = (const float*)d_in[0];
    const float* y_true = (const float*)d_in[1];
    const float* La     = (const float*)d_in[2];
    const float* lam    = (const float*)d_in[3];
    (void)in_sizes; (void)n_in; (void)out_size;

    k_fused<<<NBLK, THREADS>>>(y_pred, y_true, La, lam, (float*)d_out);
}

// round 5
// speedup vs baseline: 1.0876x; 1.0876x over previous
#include <cuda_runtime.h>
#include <cstdint>

#define CCLS 8192
#define BSZ  512
#define HH   8
#define THREADS 256
#define C4   (CCLS/4)          // 2048 float4 columns
#define NCB  16                // column blocks (128 c4-cols each)
#define NRG  64                // 8-row groups
#define NBLK (NCB*NRG)         // 1024 blocks

__device__ float    g_part[NBLK];
__device__ unsigned g_cnt = 0;   // wraps each full grid -> graph-replay-safe

__device__ __forceinline__ unsigned long long pack2(unsigned a, unsigned b) {
    unsigned long long r;
    asm("mov.b64 %0, {%1, %2};" : "=l"(r) : "r"(a), "r"(b));
    return r;
}
__device__ __forceinline__ void unpack2(unsigned long long v, unsigned& a, unsigned& b) {
    asm("mov.b64 {%0, %1}, %2;" : "=r"(a), "=r"(b) : "l"(v));
}
__device__ __forceinline__ unsigned long long fma2(unsigned long long a,
                                                   unsigned long long b,
                                                   unsigned long long c) {
    unsigned long long d;
    asm("fma.rn.f32x2 %0, %1, %2, %3;" : "=l"(d) : "l"(a), "l"(b), "l"(c));
    return d;
}

// Each (4-col, 8-row) unit is split across a thread PAIR:
//   tid 0..127  (half 0): rows rg*8+0..3, also does weights+logs+reduction input
//   tid 128..255(half 1): rows rg*8+4..7, stores its partial product to smem
// All 8 critical LDG.128 per thread are batched (only 32 data regs), and thread
// count (262144) gives 32 warps/SM residency -> ~32KB/SM in flight.
__global__ void __launch_bounds__(THREADS, 4)
k_fused(const float* __restrict__ yp, const float* __restrict__ yt,
        const float* __restrict__ La, const float* __restrict__ lam,
        float* __restrict__ out) {
    __shared__ float4 sprod[128];
    __shared__ float  shred[THREADS / 32];
    __shared__ bool   isLast;

    const int tid  = threadIdx.x;
    const int c    = tid & 127;
    const int half = tid >> 7;                 // warp-uniform
    const int cb   = blockIdx.x & (NCB - 1);
    const int rg   = blockIdx.x >> 4;          // log2(NCB)=4
    const int c4   = cb * 128 + c;
    const size_t base = (size_t)(rg * 8 + half * 4) * C4 + c4;  // float4 units
    const uint4* P = (const uint4*)yp + base;
    const uint4* T = (const uint4*)yt + base;

    // ---- batch the DRAM-critical stream: 8 x LDG.128 (32 regs) ----
    uint4 pv0 = P[0], pv1 = P[(size_t)C4], pv2 = P[(size_t)2 * C4], pv3 = P[(size_t)3 * C4];
    uint4 tv0 = T[0], tv1 = T[(size_t)C4], tv2 = T[(size_t)2 * C4], tv3 = T[(size_t)3 * C4];

    // ---- weights (half 0 only; L2-hot, overlaps main-load latency) ----
    float4 w4 = make_float4(0.f, 0.f, 0.f, 0.f);
    if (half == 0) {
        const float4* La4 = (const float4*)La;
        float4 lamA = ((const float4*)lam)[0];
        float4 lamB = ((const float4*)lam)[1];
        float lm[HH] = {lamA.x, lamA.y, lamA.z, lamA.w,
                        lamB.x, lamB.y, lamB.z, lamB.w};
#pragma unroll
        for (int h = 0; h < HH; h++) {
            float4 a = La4[(size_t)h * C4 + c4];
            w4.x = fmaf(lm[h], a.x, w4.x);
            w4.y = fmaf(lm[h], a.y, w4.y);
            w4.z = fmaf(lm[h], a.z, w4.z);
            w4.w = fmaf(lm[h], a.w, w4.w);
        }
    }

    // ---- partial product over this half's 4 rows (two f32x2 chains) ----
    const unsigned long long NEG1 = 0xBF800000BF800000ull;
    const unsigned long long SGN  = 0x8000000080000000ull;
    unsigned long long prod01 = 0x3F8000003F800000ull;
    unsigned long long prod23 = 0x3F8000003F800000ull;
#define ROWSTEP(PV, TV) do {                                                    \
        unsigned long long p01 = pack2((PV).x, (PV).y);                         \
        unsigned long long p23 = pack2((PV).z, (PV).w);                         \
        unsigned long long t01 = pack2((TV).x, (TV).y);                         \
        unsigned long long t23 = pack2((TV).z, (TV).w);                         \
        unsigned long long d01 = fma2(t01, NEG1, p01) | SGN;  /* -|p-yt| */     \
        unsigned long long d23 = fma2(t23, NEG1, p23) | SGN;                    \
        prod01 = fma2(d01, prod01, prod01);                   /* *= 1-|d| */    \
        prod23 = fma2(d23, prod23, prod23);                                     \
    } while (0)
    ROWSTEP(pv0, tv0);
    ROWSTEP(pv1, tv1);
    ROWSTEP(pv2, tv2);
    ROWSTEP(pv3, tv3);
#undef ROWSTEP

    unsigned a0, a1, a2, a3;
    unpack2(prod01, a0, a1);
    unpack2(prod23, a2, a3);

    // ---- pair exchange: upper half publishes its partial product ----
    if (half) {
        sprod[c] = make_float4(__uint_as_float(a0), __uint_as_float(a1),
                               __uint_as_float(a2), __uint_as_float(a3));
    }
    __syncthreads();

    float acc = 0.f;
    if (!half) {
        float4 o = sprod[c];
        float x0 = __uint_as_float(a0) * o.x;
        float x1 = __uint_as_float(a1) * o.y;
        float x2 = __uint_as_float(a2) * o.z;
        float x3 = __uint_as_float(a3) * o.w;
        const float CL2 = -144.26950408889634f;   // -100/ln2
        float l;
        l = fmaxf(__log2f(x0), CL2); acc = l * w4.x;
        l = fmaxf(__log2f(x1), CL2); acc = fmaf(l, w4.y, acc);
        l = fmaxf(__log2f(x2), CL2); acc = fmaf(l, w4.z, acc);
        l = fmaxf(__log2f(x3), CL2); acc = fmaf(l, w4.w, acc);
    }

    // ---- block reduction (256 threads; upper half contributes 0) ----
#pragma unroll
    for (int o = 16; o; o >>= 1) acc += __shfl_xor_sync(0xFFFFFFFFu, acc, o);
    if ((tid & 31) == 0) shred[tid >> 5] = acc;
    __syncthreads();
    if (tid < THREADS / 32) {
        float v = shred[tid];
#pragma unroll
        for (int o = (THREADS / 64); o; o >>= 1) v += __shfl_xor_sync(0xFFu, v, o);
        if (tid == 0) g_part[blockIdx.x] = v;
    }

    // ---- last-block final reduction ----
    __threadfence();
    if (tid == 0) {
        unsigned t = atomicInc(&g_cnt, NBLK - 1);
        isLast = (t == NBLK - 1);
    }
    __syncthreads();
    if (isLast) {
        float v = 0.f;
#pragma unroll
        for (int i = 0; i < NBLK / THREADS; i++)
            v += g_part[tid + i * THREADS];
#pragma unroll
        for (int o = 16; o; o >>= 1) v += __shfl_xor_sync(0xFFFFFFFFu, v, o);
        if ((tid & 31) == 0) shred[tid >> 5] = v;
        __syncthreads();
        if (tid < THREADS / 32) {
            float s = shred[tid];
#pragma unroll
            for (int o = (THREADS / 64); o; o >>= 1) s += __shfl_xor_sync(0xFFu, s, o);
            if (tid == 0)
                out[0] = s * (-0.69314718055994531f / (float)CCLS);
        }
    }
}

extern "C" void kernel_launch(void* const* d_in, const int* in_sizes, int n_in,
                              void* d_out, int out_size) {
    const float* y_pred = (const float*)d_in[0];
    const float* y_true = (const float*)d_in[1];
    const float* La     = (const float*)d_in[2];
    const float* lam    = (const float*)d_in[3];
    (void)in_sizes; (void)n_in; (void)out_size;

    k_fused<<<NBLK, THREADS>>>(y_pred, y_true, La, lam, (float*)d_out);
}

// round 6
// speedup vs baseline: 1.1000x; 1.0114x over previous
#include <cuda_runtime.h>
#include <cstdint>

#define CCLS 8192
#define BSZ  512
#define HH   8
#define RG   8                       // rows per product group (one log per 8 rows)
#define THREADS 256
#define C4   (CCLS/4)                // 2048 float4 columns
#define NBLK ((C4 * (BSZ/RG)) / THREADS)   // 512 blocks

__device__ float    g_part[NBLK];
__device__ unsigned g_cnt = 0;       // wraps each full grid -> graph-replay-safe

// Single fused kernel. Per-thread: 4 consecutive columns (one float4) x 8 rows.
//   prod_c = PROD_r (1 - |p - yt|)   (== yt?p:1-p, binary yt; La folds out:
//            masked entries contribute exactly 0 under the -100 log clamp)
//   w[c]   = sum_h lam[h]*La[h][c]   (inline, L2-hot)
//   result = sum_c w[c] * max(log2 prod_c, -100/ln2) * (-ln2/C)
// The hot path is PURE C++ (no inline asm) so ptxas can batch all 16 LDG.128;
// min-blocks=3 gives an 85-reg budget so the batch actually fits in registers.
__global__ void __launch_bounds__(THREADS, 3)
k_fused(const float* __restrict__ yp, const float* __restrict__ yt,
        const float* __restrict__ La, const float* __restrict__ lam,
        float* __restrict__ out) {
    const int tid  = threadIdx.x;
    const int unit = blockIdx.x * THREADS + tid;
    const int c4   = unit & (C4 - 1);
    const int rg   = unit >> 11;                    // log2(C4) = 11
    const size_t base = (size_t)rg * RG * C4 + c4;  // float4 units
    const float4* P = (const float4*)yp + base;
    const float4* T = (const float4*)yt + base;

    // ---- batch the DRAM-critical stream: 16 x LDG.128 ----
    float4 pv[RG], tv[RG];
#pragma unroll
    for (int r = 0; r < RG; r++) pv[r] = P[(size_t)r * C4];
#pragma unroll
    for (int r = 0; r < RG; r++) tv[r] = T[(size_t)r * C4];

    // ---- weights (L2-hot; overlaps in-flight main loads) ----
    const float4* La4 = (const float4*)La;
    const float4 lamA = ((const float4*)lam)[0];
    const float4 lamB = ((const float4*)lam)[1];
    const float lm[HH] = {lamA.x, lamA.y, lamA.z, lamA.w,
                          lamB.x, lamB.y, lamB.z, lamB.w};
    float4 w4 = make_float4(0.f, 0.f, 0.f, 0.f);
#pragma unroll
    for (int h = 0; h < HH; h++) {
        float4 a = La4[(size_t)h * C4 + c4];
        w4.x = fmaf(lm[h], a.x, w4.x);
        w4.y = fmaf(lm[h], a.y, w4.y);
        w4.z = fmaf(lm[h], a.z, w4.z);
        w4.w = fmaf(lm[h], a.w, w4.w);
    }

    // ---- four independent product chains (FADD + FFMA w/ neg-abs modifier) ----
    float p0 = 1.f, p1 = 1.f, p2 = 1.f, p3 = 1.f;
#pragma unroll
    for (int r = 0; r < RG; r++) {
        p0 = fmaf(-fabsf(pv[r].x - tv[r].x), p0, p0);   // *= (1 - |p - t|)
        p1 = fmaf(-fabsf(pv[r].y - tv[r].y), p1, p1);
        p2 = fmaf(-fabsf(pv[r].z - tv[r].z), p2, p2);
        p3 = fmaf(-fabsf(pv[r].w - tv[r].w), p3, p3);
    }

    const float CL2 = -144.26950408889634f;   // -100 / ln(2)
    float l, acc;
    l   = fmaxf(__log2f(p0), CL2); acc = l * w4.x;
    l   = fmaxf(__log2f(p1), CL2); acc = fmaf(l, w4.y, acc);
    l   = fmaxf(__log2f(p2), CL2); acc = fmaf(l, w4.z, acc);
    l   = fmaxf(__log2f(p3), CL2); acc = fmaf(l, w4.w, acc);

    // ---- block reduction ----
#pragma unroll
    for (int o = 16; o; o >>= 1) acc += __shfl_xor_sync(0xFFFFFFFFu, acc, o);
    __shared__ float shred[THREADS / 32];
    __shared__ bool  isLast;
    if ((tid & 31) == 0) shred[tid >> 5] = acc;
    __syncthreads();
    if (tid < THREADS / 32) {
        float v = shred[tid];
#pragma unroll
        for (int o = (THREADS / 64); o; o >>= 1) v += __shfl_xor_sync(0xFFu, v, o);
        if (tid == 0) g_part[blockIdx.x] = v;
    }

    // ---- last-block final reduction ----
    __threadfence();
    if (tid == 0) {
        unsigned t = atomicInc(&g_cnt, NBLK - 1);
        isLast = (t == NBLK - 1);
    }
    __syncthreads();
    if (isLast) {
        float v = g_part[tid] + g_part[tid + THREADS];
#pragma unroll
        for (int o = 16; o; o >>= 1) v += __shfl_xor_sync(0xFFFFFFFFu, v, o);
        if ((tid & 31) == 0) shred[tid >> 5] = v;
        __syncthreads();
        if (tid < THREADS / 32) {
            float s = shred[tid];
#pragma unroll
            for (int o = (THREADS / 64); o; o >>= 1) s += __shfl_xor_sync(0xFFu, s, o);
            if (tid == 0)
                out[0] = s * (-0.69314718055994531f / (float)CCLS);
        }
    }
}

extern "C" void kernel_launch(void* const* d_in, const int* in_sizes, int n_in,
                              void* d_out, int out_size) {
    const float* y_pred = (const float*)d_in[0];
    const float* y_true = (const float*)d_in[1];
    const float* La     = (const float*)d_in[2];
    const float* lam    = (const float*)d_in[3];
    (void)in_sizes; (void)n_in; (void)out_size;

    k_fused<<<NBLK, THREADS>>>(y_pred, y_true, La, lam, (float*)d_out);
}